// round 1
// baseline (speedup 1.0000x reference)
#include <cuda_runtime.h>
#include <math.h>

#define B   64
#define D   128
#define LC  1024
#define LQ  256
#define NEG_INF -1e30f

// ---------------- scratch (device globals: no allocation allowed) ----------------
__device__ float g_E[(size_t)B * LC * LQ];   // exp(S), 64 MiB
__device__ float g_M[(size_t)B * LQ * D];    // S2^T @ Ct
__device__ float g_rowsum[B * LC];
__device__ float g_colsum[B * LQ];
__device__ float g_cw1[B * LC];
__device__ float g_qw2[B * LQ];
__device__ float g_fc[B * LC];               // exp((1-cmask)*NEG_INF)  (0 or 1)
__device__ float g_fq[B * LQ];               // exp((1-qmask)*NEG_INF)

// ---------------- K0: biases, mask factors, zero accumulators ----------------
__global__ void k0_setup(const float* __restrict__ C, const float* __restrict__ Q,
                         const float* __restrict__ cmask, const float* __restrict__ qmask,
                         const float* __restrict__ w) {
    int idx = blockIdx.x * 256 + threadIdx.x;
    if (idx < B * LC) {
        int b = idx >> 10;
        int i = idx & (LC - 1);
        const float* cp = C + (size_t)b * D * LC + i;
        float s = 0.f;
#pragma unroll 4
        for (int dd = 0; dd < D; ++dd) s = fmaf(cp[(size_t)dd * LC], w[dd], s);
        g_cw1[idx] = s;
        g_fc[idx] = expf((1.0f - cmask[idx]) * NEG_INF);
        g_rowsum[idx] = 0.f;
    } else {
        int t = idx - B * LC;
        if (t < B * LQ) {
            int b = t >> 8;
            int j = t & (LQ - 1);
            const float* qp = Q + (size_t)b * D * LQ + j;
            float s = 0.f;
#pragma unroll 4
            for (int dd = 0; dd < D; ++dd) s = fmaf(qp[(size_t)dd * LQ], w[D + dd], s);
            g_qw2[t] = s;
            g_fq[t] = expf((1.0f - qmask[t]) * NEG_INF);
            g_colsum[t] = 0.f;
        }
    }
}

// ---------------- K1: E = exp(S) + row/col exp-sums -------------------------
// grid (LQ/64, LC/64, B), 256 threads, 64x64 tile, micro 4x4, K=D=128
__global__ __launch_bounds__(256) void k1_score(const float* __restrict__ C,
                                                const float* __restrict__ Q,
                                                const float* __restrict__ w) {
    int b = blockIdx.z;
    int i0 = blockIdx.y * 64;
    int j0 = blockIdx.x * 64;

    __shared__ float As[16][64];
    __shared__ float Bs[16][64];
    __shared__ float srow[64];
    __shared__ float scol[64];

    int tid = threadIdx.x;
    int tm = tid & 15;      // row group (i)
    int tn = tid >> 4;      // col group (j)
    if (tid < 64) { srow[tid] = 0.f; scol[tid] = 0.f; }

    float acc[4][4];
#pragma unroll
    for (int r = 0; r < 4; ++r)
#pragma unroll
        for (int c = 0; c < 4; ++c) acc[r][c] = 0.f;

    const float* Cb = C + (size_t)b * D * LC;
    const float* Qb = Q + (size_t)b * D * LQ;

    int t4 = tid * 4;
    int lkk = t4 >> 6;      // 0..15
    int lii = t4 & 63;      // 0..60 step 4

    for (int k0 = 0; k0 < D; k0 += 16) {
        float w3v = w[2 * D + k0 + lkk];
        float4 v = *(const float4*)(Cb + (size_t)(k0 + lkk) * LC + i0 + lii);
        v.x *= w3v; v.y *= w3v; v.z *= w3v; v.w *= w3v;
        float4 u = *(const float4*)(Qb + (size_t)(k0 + lkk) * LQ + j0 + lii);
        __syncthreads();
        *(float4*)&As[lkk][lii] = v;
        *(float4*)&Bs[lkk][lii] = u;
        __syncthreads();
#pragma unroll
        for (int kk = 0; kk < 16; ++kk) {
            float4 a = *(const float4*)&As[kk][tm * 4];
            float4 bq = *(const float4*)&Bs[kk][tn * 4];
            float av[4] = {a.x, a.y, a.z, a.w};
            float bv[4] = {bq.x, bq.y, bq.z, bq.w};
#pragma unroll
            for (int r = 0; r < 4; ++r)
#pragma unroll
                for (int c = 0; c < 4; ++c) acc[r][c] = fmaf(av[r], bv[c], acc[r][c]);
        }
    }

    // epilogue: biases, exp, store E, reduce row/col sums
    int ib = i0 + tm * 4;
    int jb = j0 + tn * 4;
    float cw[4], fcv[4], qw[4], fqv[4];
#pragma unroll
    for (int r = 0; r < 4; ++r) { cw[r] = g_cw1[b * LC + ib + r]; fcv[r] = g_fc[b * LC + ib + r]; }
#pragma unroll
    for (int c = 0; c < 4; ++c) { qw[c] = g_qw2[b * LQ + jb + c]; fqv[c] = g_fq[b * LQ + jb + c]; }

    float rowp[4] = {0.f, 0.f, 0.f, 0.f};
    float colp[4] = {0.f, 0.f, 0.f, 0.f};
    float ev[4][4];
#pragma unroll
    for (int r = 0; r < 4; ++r) {
#pragma unroll
        for (int c = 0; c < 4; ++c) {
            float e = expf(acc[r][c] + cw[r] + qw[c]);
            ev[r][c] = e;
            rowp[r] = fmaf(e, fqv[c], rowp[r]);
            colp[c] = fmaf(e, fcv[r], colp[c]);
        }
    }
#pragma unroll
    for (int r = 0; r < 4; ++r) {
        *(float4*)(g_E + ((size_t)b * LC + ib + r) * LQ + jb) =
            make_float4(ev[r][0], ev[r][1], ev[r][2], ev[r][3]);
    }
#pragma unroll
    for (int r = 0; r < 4; ++r) atomicAdd(&srow[tm * 4 + r], rowp[r]);
#pragma unroll
    for (int c = 0; c < 4; ++c) atomicAdd(&scol[tn * 4 + c], colp[c]);
    __syncthreads();
    if (tid < 64)       atomicAdd(&g_rowsum[b * LC + i0 + tid], srow[tid]);
    else if (tid < 128) atomicAdd(&g_colsum[b * LQ + j0 + tid - 64], scol[tid - 64]);
}

// ---------------- K4: M[b,j,dd] = (sum_i E[i,j]*fc[i]*C[dd,i]) / colsum[j] ---
// grid (D/64, LQ/64, B), K = LC = 1024
__global__ __launch_bounds__(256) void k4_m(const float* __restrict__ C) {
    int b = blockIdx.z;
    int j0 = blockIdx.y * 64;
    int dd0 = blockIdx.x * 64;

    __shared__ float As[16][64];   // [kk=i][m=j]
    __shared__ float Bs[16][64];   // [kk=i][n=dd]

    int tid = threadIdx.x;
    int tm = tid & 15;   // j group
    int tn = tid >> 4;   // dd group

    float acc[4][4];
#pragma unroll
    for (int r = 0; r < 4; ++r)
#pragma unroll
        for (int c = 0; c < 4; ++c) acc[r][c] = 0.f;

    const float* Cb = C + (size_t)b * D * LC;
    const float* Eb = g_E + (size_t)b * LC * LQ;

    int t4 = tid * 4;
    int akk = t4 >> 6, amb = t4 & 63;        // direct load (E)
    int bnr = tid >> 2, bkb = (tid & 3) * 4; // transpose load (C)

    for (int k0 = 0; k0 < LC; k0 += 16) {
        float fcv = g_fc[b * LC + k0 + akk];
        float4 v = *(const float4*)(Eb + (size_t)(k0 + akk) * LQ + j0 + amb);
        v.x *= fcv; v.y *= fcv; v.z *= fcv; v.w *= fcv;
        float4 u = *(const float4*)(Cb + (size_t)(dd0 + bnr) * LC + k0 + bkb);
        __syncthreads();
        *(float4*)&As[akk][amb] = v;
        Bs[bkb + 0][bnr] = u.x;
        Bs[bkb + 1][bnr] = u.y;
        Bs[bkb + 2][bnr] = u.z;
        Bs[bkb + 3][bnr] = u.w;
        __syncthreads();
#pragma unroll
        for (int kk = 0; kk < 16; ++kk) {
            float4 a = *(const float4*)&As[kk][tm * 4];
            float4 bq = *(const float4*)&Bs[kk][tn * 4];
            float av[4] = {a.x, a.y, a.z, a.w};
            float bv[4] = {bq.x, bq.y, bq.z, bq.w};
#pragma unroll
            for (int r = 0; r < 4; ++r)
#pragma unroll
                for (int c = 0; c < 4; ++c) acc[r][c] = fmaf(av[r], bv[c], acc[r][c]);
        }
    }

    float cinv[4];
#pragma unroll
    for (int r = 0; r < 4; ++r) cinv[r] = 1.0f / g_colsum[b * LQ + j0 + tm * 4 + r];
#pragma unroll
    for (int r = 0; r < 4; ++r) {
        float4 m4 = make_float4(acc[r][0] * cinv[r], acc[r][1] * cinv[r],
                                acc[r][2] * cinv[r], acc[r][3] * cinv[r]);
        *(float4*)(g_M + ((size_t)b * LQ + j0 + tm * 4 + r) * D + dd0 + tn * 4) = m4;
    }
}

// ---------------- K5: A & Bmat fused + all 4 output channels -----------------
// grid (D/64, LC/64, B), K = LQ = 256
__global__ __launch_bounds__(256) void k5_out(const float* __restrict__ C,
                                              const float* __restrict__ Q,
                                              float* __restrict__ out) {
    int b = blockIdx.z;
    int i0 = blockIdx.y * 64;
    int dd0 = blockIdx.x * 64;

    __shared__ float As[16][64];   // [kk=j][m=i]  E*fq
    __shared__ float Bq[16][64];   // [kk=j][n=dd] Q
    __shared__ float Bm[16][64];   // [kk=j][n=dd] M
    __shared__ float fqs[LQ];

    int tid = threadIdx.x;
    int tm = tid & 15;   // i group
    int tn = tid >> 4;   // dd group
    fqs[tid] = g_fq[b * LQ + tid];

    float accA[4][4], accB[4][4];
#pragma unroll
    for (int r = 0; r < 4; ++r)
#pragma unroll
        for (int c = 0; c < 4; ++c) { accA[r][c] = 0.f; accB[r][c] = 0.f; }

    const float* Cb = C + (size_t)b * D * LC;
    const float* Qb = Q + (size_t)b * D * LQ;
    const float* Eb = g_E + (size_t)b * LC * LQ;
    const float* Mb = g_M + (size_t)b * LQ * D;

    int anr = tid >> 2, akb = (tid & 3) * 4;       // transpose loads (E, Q)
    int bkk = (tid * 4) >> 6, bnb = (tid * 4) & 63; // direct load (M)

    for (int k0 = 0; k0 < LQ; k0 += 16) {
        float4 ev = *(const float4*)(Eb + (size_t)(i0 + anr) * LQ + k0 + akb);
        float4 qv = *(const float4*)(Qb + (size_t)(dd0 + anr) * LQ + k0 + akb);
        float4 mv = *(const float4*)(Mb + (size_t)(k0 + bkk) * D + dd0 + bnb);
        __syncthreads();
        As[akb + 0][anr] = ev.x * fqs[k0 + akb + 0];
        As[akb + 1][anr] = ev.y * fqs[k0 + akb + 1];
        As[akb + 2][anr] = ev.z * fqs[k0 + akb + 2];
        As[akb + 3][anr] = ev.w * fqs[k0 + akb + 3];
        Bq[akb + 0][anr] = qv.x;
        Bq[akb + 1][anr] = qv.y;
        Bq[akb + 2][anr] = qv.z;
        Bq[akb + 3][anr] = qv.w;
        *(float4*)&Bm[bkk][bnb] = mv;
        __syncthreads();
#pragma unroll
        for (int kk = 0; kk < 16; ++kk) {
            float4 a = *(const float4*)&As[kk][tm * 4];
            float4 q4 = *(const float4*)&Bq[kk][tn * 4];
            float4 m4 = *(const float4*)&Bm[kk][tn * 4];
            float av[4] = {a.x, a.y, a.z, a.w};
            float qv4[4] = {q4.x, q4.y, q4.z, q4.w};
            float mv4[4] = {m4.x, m4.y, m4.z, m4.w};
#pragma unroll
            for (int r = 0; r < 4; ++r)
#pragma unroll
                for (int c = 0; c < 4; ++c) {
                    accA[r][c] = fmaf(av[r], qv4[c], accA[r][c]);
                    accB[r][c] = fmaf(av[r], mv4[c], accB[r][c]);
                }
        }
    }

    float rinv[4];
#pragma unroll
    for (int r = 0; r < 4; ++r) rinv[r] = 1.0f / g_rowsum[b * LC + i0 + tm * 4 + r];

    size_t ob = (size_t)b * 4 * D * LC;
    int i = i0 + tm * 4;
#pragma unroll
    for (int c = 0; c < 4; ++c) {
        int dd = dd0 + tn * 4 + c;
        float4 c4 = *(const float4*)(Cb + (size_t)dd * LC + i);
        float4 a4 = make_float4(accA[0][c] * rinv[0], accA[1][c] * rinv[1],
                                accA[2][c] * rinv[2], accA[3][c] * rinv[3]);
        float4 b4 = make_float4(accB[0][c] * rinv[0], accB[1][c] * rinv[1],
                                accB[2][c] * rinv[2], accB[3][c] * rinv[3]);
        *(float4*)(out + ob + (size_t)dd * LC + i) = c4;                              // Ct
        *(float4*)(out + ob + (size_t)(D + dd) * LC + i) = a4;                        // A
        *(float4*)(out + ob + (size_t)(2 * D + dd) * LC + i) =
            make_float4(c4.x * a4.x, c4.y * a4.y, c4.z * a4.z, c4.w * a4.w);          // Ct*A
        *(float4*)(out + ob + (size_t)(3 * D + dd) * LC + i) =
            make_float4(c4.x * b4.x, c4.y * b4.y, c4.z * b4.z, c4.w * b4.w);          // Ct*Bmat
    }
}

// ---------------- launch ------------------------------------------------------
extern "C" void kernel_launch(void* const* d_in, const int* in_sizes, int n_in,
                              void* d_out, int out_size) {
    const float* C = (const float*)d_in[0];
    const float* Q = (const float*)d_in[1];
    const float* cmask = (const float*)d_in[2];
    const float* qmask = (const float*)d_in[3];
    const float* w = (const float*)d_in[4];
    float* out = (float*)d_out;

    k0_setup<<<(B * LC + B * LQ) / 256, 256>>>(C, Q, cmask, qmask, w);

    dim3 g1(LQ / 64, LC / 64, B);
    k1_score<<<g1, 256>>>(C, Q, w);

    dim3 g4(D / 64, LQ / 64, B);
    k4_m<<<g4, 256>>>(C);

    dim3 g5(D / 64, LC / 64, B);
    k5_out<<<g5, 256>>>(C, Q, out);
}